// round 13
// baseline (speedup 1.0000x reference)
#include <cuda_runtime.h>
#include <cuda_fp16.h>
#include <cstdint>

#define N_NODES 100000
#define DIN 256
#define DOUT 256
#define MAX_EDGES 6400000
#define MCHUNK 25088            // 196 * 128, so gemm blocks never straddle chunks
#define NCHUNK 4

#define STAGES 4
#define SW 12                       // tile row stride in words (48B)
#define A_STG (128 * SW)
#define B_STG (128 * SW)
#define SMEM_BYTES (STAGES * (A_STG + B_STG) * 4)   // 49152

// ---- device-global scratch (allocation-free) ----
__device__ __half g_Xh[(size_t)N_NODES * DIN];   // fp16(X)
__device__ __half g_Wth[DIN * DOUT];             // fp16(W^T) [n][k]
__device__ __half g_Yh[(size_t)N_NODES * DOUT];  // fp16(X @ W)
__device__ float2 g_edges[MAX_EDGES];
__device__ int    g_cnt[N_NODES];
__device__ int    g_start[N_NODES];
__device__ int    g_cur[N_NODES];
__device__ int    g_bsum[128];

// ---------------------------------------------------------------------------
__device__ __forceinline__ void cp16(uint32_t dst, const void* src, int bytes) {
    asm volatile("cp.async.cg.shared.global [%0], [%1], 16, %2;"
                 :: "r"(dst), "l"(src), "r"(bytes));
}

// ---------------------------------------------------------------------------
// Pre-converts (fp32 -> fp16, RNE)
// ---------------------------------------------------------------------------
__global__ void cvt_x_chunk(const float* __restrict__ X, int base8, int n8) {
    int i = blockIdx.x * blockDim.x + threadIdx.x;
    if (i >= n8) return;
    i += base8;
    float4 v0 = __ldcs(((const float4*)X) + 2 * i);
    float4 v1 = __ldcs(((const float4*)X) + 2 * i + 1);
    __half2 h[4];
    h[0] = __floats2half2_rn(v0.x, v0.y);
    h[1] = __floats2half2_rn(v0.z, v0.w);
    h[2] = __floats2half2_rn(v1.x, v1.y);
    h[3] = __floats2half2_rn(v1.z, v1.w);
    __stcs((uint4*)(g_Xh + (size_t)i * 8), *(uint4*)h);
}

// g_Wth[n][k] = fp16(W[k][n])
__global__ void cvt_wt(const float* __restrict__ W) {
    int idx = blockIdx.x * blockDim.x + threadIdx.x;
    int n = idx >> 8, k = idx & 255;
    g_Wth[idx] = __float2half_rn(W[k * DOUT + n]);
}

// ---------------------------------------------------------------------------
// GEMM chunk: rows [rowBase, rowEnd). fp16 mma.sync.m16n8k16, fp32 accum.
// 128x128 block tile, BK=16, 256 thr (8 warps 4x2), 4-stage cp.async,
// ldmatrix.x4 fragment loads (conflict-free with 48B row stride).
// ---------------------------------------------------------------------------
__global__ __launch_bounds__(256, 2)
void gemm_f16(int rowBase, int rowEnd) {
    extern __shared__ uint32_t smem[];
    uint32_t* Asm = smem;
    uint32_t* Bsm = smem + STAGES * A_STG;

    int t = threadIdx.x;
    int lane = t & 31, wid = t >> 5;
    int warp_m = wid & 3;
    int warp_n = wid >> 2;
    int gid = lane >> 2;
    int tig = lane & 3;

    int bRow = rowBase + blockIdx.y * 128;
    int bCol = blockIdx.x * 128;

    int l_r = t >> 1, l_h = t & 1;
    int growA = bRow + l_r;
    int aBytes = (growA < rowEnd) ? 16 : 0;
    const __half* aSrc = g_Xh + (size_t)(growA < rowEnd ? growA : 0) * DIN + l_h * 8;
    const __half* bSrc = g_Wth + (size_t)(bCol + l_r) * DIN + l_h * 8;

    uint32_t aD[STAGES], bD[STAGES];
    #pragma unroll
    for (int s = 0; s < STAGES; s++) {
        aD[s] = (uint32_t)__cvta_generic_to_shared(Asm + s * A_STG + l_r * SW + l_h * 4);
        bD[s] = (uint32_t)__cvta_generic_to_shared(Bsm + s * B_STG + l_r * SW + l_h * 4);
    }

    int lj = lane >> 3;
    int lr = lane & 7;
    uint32_t offA[2];
    #pragma unroll
    for (int mt = 0; mt < 2; mt++) {
        int row = warp_m * 32 + mt * 16 + (lj & 1) * 8 + lr;
        offA[mt] = row * (SW * 4) + (lj >> 1) * 16;
    }
    uint32_t offB[4];
    #pragma unroll
    for (int q = 0; q < 4; q++) {
        int nrow = warp_n * 64 + q * 16 + (lj >> 1) * 8 + lr;
        offB[q] = nrow * (SW * 4) + (lj & 1) * 16;
    }
    uint32_t aBase = (uint32_t)__cvta_generic_to_shared(Asm);
    uint32_t bBase = (uint32_t)__cvta_generic_to_shared(Bsm);

    float c[2][8][4] = {};

    const int NIT = DIN / 16;
    #pragma unroll
    for (int s = 0; s < STAGES - 1; s++) {
        int k0 = s * 16;
        cp16(aD[s], aSrc + k0, aBytes);
        cp16(bD[s], bSrc + k0, 16);
        asm volatile("cp.async.commit_group;");
    }

    for (int it = 0; it < NIT; it++) {
        asm volatile("cp.async.wait_group %0;" :: "n"(STAGES - 2));
        __syncthreads();

        int kt = it + STAGES - 1;
        if (kt < NIT) {
            int s = kt & (STAGES - 1);
            int k0 = kt * 16;
            cp16(aD[s], aSrc + k0, aBytes);
            cp16(bD[s], bSrc + k0, 16);
        }
        asm volatile("cp.async.commit_group;");

        int p = it & (STAGES - 1);
        uint32_t stA = aBase + p * (A_STG * 4);
        uint32_t stB = bBase + p * (B_STG * 4);

        uint32_t a[2][4];
        #pragma unroll
        for (int mt = 0; mt < 2; mt++) {
            asm volatile(
                "ldmatrix.sync.aligned.m8n8.x4.shared.b16 {%0,%1,%2,%3}, [%4];"
                : "=r"(a[mt][0]), "=r"(a[mt][1]), "=r"(a[mt][2]), "=r"(a[mt][3])
                : "r"(stA + offA[mt]));
        }
        uint32_t b[8][2];
        #pragma unroll
        for (int q = 0; q < 4; q++) {
            asm volatile(
                "ldmatrix.sync.aligned.m8n8.x4.shared.b16 {%0,%1,%2,%3}, [%4];"
                : "=r"(b[2 * q][0]), "=r"(b[2 * q][1]),
                  "=r"(b[2 * q + 1][0]), "=r"(b[2 * q + 1][1])
                : "r"(stB + offB[q]));
        }
        #pragma unroll
        for (int mt = 0; mt < 2; mt++)
            #pragma unroll
            for (int nt = 0; nt < 8; nt++) {
                asm volatile(
                    "mma.sync.aligned.m16n8k16.row.col.f32.f16.f16.f32 "
                    "{%0,%1,%2,%3}, {%4,%5,%6,%7}, {%8,%9}, {%0,%1,%2,%3};"
                    : "+f"(c[mt][nt][0]), "+f"(c[mt][nt][1]),
                      "+f"(c[mt][nt][2]), "+f"(c[mt][nt][3])
                    : "r"(a[mt][0]), "r"(a[mt][1]), "r"(a[mt][2]), "r"(a[mt][3]),
                      "r"(b[nt][0]), "r"(b[nt][1]));
            }
    }

    #pragma unroll
    for (int mt = 0; mt < 2; mt++) {
        int r0 = bRow + warp_m * 32 + mt * 16 + gid;
        int r1 = r0 + 8;
        #pragma unroll
        for (int nt = 0; nt < 8; nt++) {
            int gcol = bCol + warp_n * 64 + nt * 8 + 2 * tig;
            if (r0 < rowEnd)
                *(__half2*)(g_Yh + (size_t)r0 * DOUT + gcol) =
                    __floats2half2_rn(c[mt][nt][0], c[mt][nt][1]);
            if (r1 < rowEnd)
                *(__half2*)(g_Yh + (size_t)r1 * DOUT + gcol) =
                    __floats2half2_rn(c[mt][nt][2], c[mt][nt][3]);
        }
    }
}

// ---- host-side resources, created before harness checkpoints ----
static cudaStream_t g_s2, g_s3;
static cudaEvent_t  g_evFork, g_evSort, g_evWt, g_evG, g_evC[NCHUNK];
namespace {
struct _HostInit {
    _HostInit() {
        cudaStreamCreateWithFlags(&g_s2, cudaStreamNonBlocking);
        cudaStreamCreateWithFlags(&g_s3, cudaStreamNonBlocking);
        cudaEventCreateWithFlags(&g_evFork, cudaEventDisableTiming);
        cudaEventCreateWithFlags(&g_evSort, cudaEventDisableTiming);
        cudaEventCreateWithFlags(&g_evWt,   cudaEventDisableTiming);
        cudaEventCreateWithFlags(&g_evG,    cudaEventDisableTiming);
        for (int i = 0; i < NCHUNK; i++)
            cudaEventCreateWithFlags(&g_evC[i], cudaEventDisableTiming);
        cudaFuncSetAttribute(gemm_f16, cudaFuncAttributeMaxDynamicSharedMemorySize,
                             SMEM_BYTES);
    }
} _hostInit;
}

// ---------------------------------------------------------------------------
// Counting-sort pipeline (forked stream)
// ---------------------------------------------------------------------------
__global__ void zero_cnt(int n) {
    int i = blockIdx.x * blockDim.x + threadIdx.x;
    if (i < n) g_cnt[i] = 0;
}

__global__ void hist2(const int* __restrict__ r1, int n1,
                      const int* __restrict__ r2, int n2) {
    int i = blockIdx.x * blockDim.x + threadIdx.x;
    if (i < n1) {
        atomicAdd(&g_cnt[__ldcs(r1 + i)], 1);
    } else {
        int j = i - n1;
        if (j < n2) atomicAdd(&g_cnt[__ldcs(r2 + j)], 1);
    }
}

__global__ void scan_local(int n) {
    __shared__ int buf[1024];
    int tid = threadIdx.x;
    int i = blockIdx.x * 1024 + tid;
    int v = (i < n) ? g_cnt[i] : 0;
    buf[tid] = v;
    __syncthreads();
    #pragma unroll
    for (int s = 1; s < 1024; s <<= 1) {
        int t = (tid >= s) ? buf[tid - s] : 0;
        __syncthreads();
        buf[tid] += t;
        __syncthreads();
    }
    if (i < n) g_start[i] = buf[tid] - v;
    if (tid == 1023) g_bsum[blockIdx.x] = buf[1023];
}

__global__ void scan_bsum(int nb) {
    __shared__ int buf[128];
    int tid = threadIdx.x;
    int v = (tid < nb) ? g_bsum[tid] : 0;
    buf[tid] = v;
    __syncthreads();
    #pragma unroll
    for (int s = 1; s < 128; s <<= 1) {
        int t = (tid >= s) ? buf[tid - s] : 0;
        __syncthreads();
        buf[tid] += t;
        __syncthreads();
    }
    if (tid < nb) g_bsum[tid] = buf[tid] - v;
}

__global__ void scan_add(int n) {
    int i = blockIdx.x * 1024 + threadIdx.x;
    if (i < n) {
        int s = g_start[i] + g_bsum[blockIdx.x];
        g_start[i] = s;
        g_cur[i]   = s;
    }
}

__global__ void fill2(const int* __restrict__ r1, const int* __restrict__ c1,
                      const float* __restrict__ v1, int n1,
                      const int* __restrict__ r2, const int* __restrict__ c2,
                      const float* __restrict__ v2, int n2) {
    int i = blockIdx.x * blockDim.x + threadIdx.x;
    if (i < n1) {
        int r = __ldcs(r1 + i);
        int p = atomicAdd(&g_cur[r], 1);
        g_edges[p] = make_float2(__int_as_float(__ldcs(c1 + i)), __ldcs(v1 + i));
    } else {
        int j = i - n1;
        if (j < n2) {
            int r = __ldcs(r2 + j);
            int p = atomicAdd(&g_cur[r], 1);
            g_edges[p] = make_float2(__int_as_float(__ldcs(c2 + j)), __ldcs(v2 + j));
        }
    }
}

// ---------------------------------------------------------------------------
// Accumulate: one warp per row. out[row,:] = bias + sum_j val_j * Yh[col_j,:]
// ---------------------------------------------------------------------------
__global__ void accumulate(const float* __restrict__ bias, float* __restrict__ out, int M) {
    int row  = (blockIdx.x * blockDim.x + threadIdx.x) >> 5;
    if (row >= M) return;
    int lane = threadIdx.x & 31;

    int beg = g_start[row];
    int end = g_cur[row];

    float acc[8];
    *(float4*)(acc)     = ((const float4*)bias)[lane * 2];
    *(float4*)(acc + 4) = ((const float4*)bias)[lane * 2 + 1];

    int j = beg;
    for (; j + 3 < end; j += 4) {
        float2 e[4];
        #pragma unroll
        for (int u = 0; u < 4; u++) e[u] = __ldcs(&g_edges[j + u]);
        uint4 q[4];
        #pragma unroll
        for (int u = 0; u < 4; u++) {
            int c = __float_as_int(e[u].x);
            q[u] = __ldg((const uint4*)(g_Yh + (size_t)c * DOUT + lane * 8));
        }
        #pragma unroll
        for (int u = 0; u < 4; u++) {
            float v = e[u].y;
            const __half2* h = (const __half2*)&q[u];
            #pragma unroll
            for (int p = 0; p < 4; p++) {
                float2 f = __half22float2(h[p]);
                acc[2 * p]     += v * f.x;
                acc[2 * p + 1] += v * f.y;
            }
        }
    }
    for (; j < end; j++) {
        float2 e = __ldcs(&g_edges[j]);
        int c = __float_as_int(e.x);  float v = e.y;
        uint4 q = __ldg((const uint4*)(g_Yh + (size_t)c * DOUT + lane * 8));
        const __half2* h = (const __half2*)&q;
        #pragma unroll
        for (int p = 0; p < 4; p++) {
            float2 f = __half22float2(h[p]);
            acc[2 * p]     += v * f.x;
            acc[2 * p + 1] += v * f.y;
        }
    }

    float4* o = (float4*)(out + (size_t)row * DOUT);
    __stcs(o + lane * 2,     *(float4*)(acc));
    __stcs(o + lane * 2 + 1, *(float4*)(acc + 4));
}

// ---------------------------------------------------------------------------
extern "C" void kernel_launch(void* const* d_in, const int* in_sizes, int n_in,
                              void* d_out, int out_size) {
    const float* X    = (const float*)d_in[0];
    const int*   Lr   = (const int*)d_in[1];
    const int*   Lc   = (const int*)d_in[2];
    const float* Lv   = (const float*)d_in[3];
    const int*   L3r  = (const int*)d_in[4];
    const int*   L3c  = (const int*)d_in[5];
    const float* L3v  = (const float*)d_in[6];
    const float* Wt   = (const float*)d_in[7];
    const float* bias = (const float*)d_in[8];
    float* out = (float*)d_out;

    int M    = in_sizes[0] / DIN;   // 100000
    int nnz1 = in_sizes[1];
    int nnz2 = in_sizes[4];
    int nnzT = nnz1 + nnz2;

    // ---- fork: sort on s2 ----
    cudaEventRecord(g_evFork, 0);
    cudaStreamWaitEvent(g_s2, g_evFork, 0);

    int nblk = (M + 1023) / 1024;
    zero_cnt<<<(M + 255) / 256, 256, 0, g_s2>>>(M);
    hist2<<<(nnzT + 255) / 256, 256, 0, g_s2>>>(Lr, nnz1, L3r, nnz2);
    scan_local<<<nblk, 1024, 0, g_s2>>>(M);
    scan_bsum<<<1, 128, 0, g_s2>>>(nblk);
    scan_add<<<nblk, 1024, 0, g_s2>>>(M);
    fill2<<<(nnzT + 255) / 256, 256, 0, g_s2>>>(Lr, Lc, Lv, nnz1, L3r, L3c, L3v, nnz2);
    cudaEventRecord(g_evSort, g_s2);

    // ---- main: cvt_wt, then cvt_x chunks; s3: gemm chunks pipelined ----
    cvt_wt<<<(DIN * DOUT + 255) / 256, 256>>>(Wt);
    cudaEventRecord(g_evWt, 0);
    cudaStreamWaitEvent(g_s3, g_evWt, 0);

    for (int ch = 0; ch < NCHUNK; ch++) {
        int rb = ch * MCHUNK;
        if (rb >= M) break;
        int re = (rb + MCHUNK < M) ? rb + MCHUNK : M;
        int base8 = rb * (DIN / 8);
        int n8 = (re - rb) * (DIN / 8);
        cvt_x_chunk<<<(n8 + 255) / 256, 256>>>(X, base8, n8);
        cudaEventRecord(g_evC[ch], 0);
        cudaStreamWaitEvent(g_s3, g_evC[ch], 0);
        dim3 gg(2, (re - rb + 127) / 128);
        gemm_f16<<<gg, 256, SMEM_BYTES, g_s3>>>(rb, re);
    }
    cudaEventRecord(g_evG, g_s3);

    // ---- join sort + gemm, then accumulate ----
    cudaStreamWaitEvent(0, g_evSort, 0);
    cudaStreamWaitEvent(0, g_evG, 0);
    int blocks = (M * 32 + 255) / 256;
    accumulate<<<blocks, 256>>>(bias, out, M);
}

// round 14
// speedup vs baseline: 1.0557x; 1.0557x over previous
#include <cuda_runtime.h>
#include <cuda_fp16.h>
#include <cstdint>

#define N_NODES 100000
#define DIN 256
#define DOUT 256
#define MAX_EDGES 6400000

#define STAGES 3
#define SW 20                        // tile row stride in words (80B)
#define A_STG (128 * SW)             // words per A stage
#define B_STG (128 * SW)             // words per B stage
#define SMEM_BYTES (STAGES * (A_STG + B_STG) * 4)   // 61440

// ---- device-global scratch (allocation-free) ----
__device__ __half g_Xh[(size_t)N_NODES * DIN];   // fp16(X)
__device__ __half g_Wth[DIN * DOUT];             // fp16(W^T) [n][k]
__device__ __half g_Yh[(size_t)N_NODES * DOUT];  // fp16(X @ W)
__device__ float2 g_edges[MAX_EDGES];
__device__ int    g_cnt[N_NODES];
__device__ int    g_start[N_NODES];
__device__ int    g_cur[N_NODES];
__device__ int    g_bsum[128];

// ---------------------------------------------------------------------------
__device__ __forceinline__ void cp16(uint32_t dst, const void* src, int bytes) {
    asm volatile("cp.async.cg.shared.global [%0], [%1], 16, %2;"
                 :: "r"(dst), "l"(src), "r"(bytes));
}

// ---------------------------------------------------------------------------
// Pre-converts (fp32 -> fp16, RNE)
// ---------------------------------------------------------------------------
__global__ void cvt_x(const float* __restrict__ X, int total8) {
    int i = blockIdx.x * blockDim.x + threadIdx.x;
    if (i >= total8) return;
    float4 v0 = __ldcs(((const float4*)X) + 2 * i);
    float4 v1 = __ldcs(((const float4*)X) + 2 * i + 1);
    __half2 h[4];
    h[0] = __floats2half2_rn(v0.x, v0.y);
    h[1] = __floats2half2_rn(v0.z, v0.w);
    h[2] = __floats2half2_rn(v1.x, v1.y);
    h[3] = __floats2half2_rn(v1.z, v1.w);
    __stcs((uint4*)(g_Xh + (size_t)i * 8), *(uint4*)h);
}

// g_Wth[n][k] = fp16(W[k][n])
__global__ void cvt_wt(const float* __restrict__ W) {
    int idx = blockIdx.x * blockDim.x + threadIdx.x;
    int n = idx >> 8, k = idx & 255;
    g_Wth[idx] = __float2half_rn(W[k * DOUT + n]);
}

// ---------------------------------------------------------------------------
// GEMM: g_Yh = X @ W via fp16 mma.sync.m16n8k16 (fp32 accumulate)
// 128x128 block tile, BK=32, 256 thr (8 warps 4x2), 3-stage cp.async,
// ldmatrix.x4 fragment loads (conflict-free with 80B row stride).
// ---------------------------------------------------------------------------
__global__ __launch_bounds__(256, 2)
void gemm_f16(int M) {
    extern __shared__ uint32_t smem[];
    uint32_t* Asm = smem;                  // STAGES * A_STG words
    uint32_t* Bsm = smem + STAGES * A_STG;

    int t = threadIdx.x;
    int lane = t & 31, wid = t >> 5;
    int warp_m = wid & 3;
    int warp_n = wid >> 2;
    int gid = lane >> 2;
    int tig = lane & 3;

    int bRow = blockIdx.y * 128;
    int bCol = blockIdx.x * 128;

    // loaders: row = t>>1 (0..127), half = t&1; each thread 2x16B contiguous
    int l_r = t >> 1, l_h = t & 1;
    int growA = bRow + l_r;
    int aBytes = (growA < M) ? 16 : 0;
    const __half* aSrc = g_Xh + (size_t)(growA < M ? growA : 0) * DIN + l_h * 16;
    const __half* bSrc = g_Wth + (size_t)(bCol + l_r) * DIN + l_h * 16;

    uint32_t aD[STAGES], bD[STAGES];
    #pragma unroll
    for (int s = 0; s < STAGES; s++) {
        aD[s] = (uint32_t)__cvta_generic_to_shared(Asm + s * A_STG + l_r * SW + l_h * 8);
        bD[s] = (uint32_t)__cvta_generic_to_shared(Bsm + s * B_STG + l_r * SW + l_h * 8);
    }

    // ldmatrix lane offsets (bytes, relative to stage base)
    int lj = lane >> 3;          // matrix index 0..3
    int lr = lane & 7;           // row within matrix
    uint32_t offA[2];
    #pragma unroll
    for (int mt = 0; mt < 2; mt++) {
        int row = warp_m * 32 + mt * 16 + (lj & 1) * 8 + lr;
        offA[mt] = row * (SW * 4) + (lj >> 1) * 16;
    }
    uint32_t offB[4];
    #pragma unroll
    for (int q = 0; q < 4; q++) {
        int nrow = warp_n * 64 + q * 16 + (lj >> 1) * 8 + lr;
        offB[q] = nrow * (SW * 4) + (lj & 1) * 16;
    }
    uint32_t aBase = (uint32_t)__cvta_generic_to_shared(Asm);
    uint32_t bBase = (uint32_t)__cvta_generic_to_shared(Bsm);

    float c[2][8][4] = {};

    const int NIT = DIN / 32;   // 8
    // prefetch first STAGES-1 tiles
    #pragma unroll
    for (int s = 0; s < STAGES - 1; s++) {
        int k0 = s * 32;
        cp16(aD[s],      aSrc + k0,     aBytes);
        cp16(aD[s] + 16, aSrc + k0 + 8, aBytes);   // wrong? see below
        cp16(bD[s],      bSrc + k0,     16);
        cp16(bD[s] + 16, bSrc + k0 + 8, 16);
        asm volatile("cp.async.commit_group;");
    }

    #pragma unroll
    for (int it = 0; it < NIT; it++) {
        asm volatile("cp.async.wait_group %0;" :: "n"(STAGES - 2));
        __syncthreads();

        int kt = it + STAGES - 1;
        if (kt < NIT) {
            int s = kt % STAGES;
            int k0 = kt * 32;
            cp16(aD[s],      aSrc + k0,     aBytes);
            cp16(aD[s] + 16, aSrc + k0 + 8, aBytes);
            cp16(bD[s],      bSrc + k0,     16);
            cp16(bD[s] + 16, bSrc + k0 + 8, 16);
        }
        asm volatile("cp.async.commit_group;");

        int p = it % STAGES;
        uint32_t stA = aBase + p * (A_STG * 4);
        uint32_t stB = bBase + p * (B_STG * 4);

        #pragma unroll
        for (int ks = 0; ks < 2; ks++) {
            uint32_t kb = ks * 32;   // 16 halfs = 32 bytes
            uint32_t a[2][4];
            #pragma unroll
            for (int mt = 0; mt < 2; mt++) {
                asm volatile(
                    "ldmatrix.sync.aligned.m8n8.x4.shared.b16 {%0,%1,%2,%3}, [%4];"
                    : "=r"(a[mt][0]), "=r"(a[mt][1]), "=r"(a[mt][2]), "=r"(a[mt][3])
                    : "r"(stA + offA[mt] + kb));
            }
            uint32_t b[8][2];
            #pragma unroll
            for (int q = 0; q < 4; q++) {
                asm volatile(
                    "ldmatrix.sync.aligned.m8n8.x4.shared.b16 {%0,%1,%2,%3}, [%4];"
                    : "=r"(b[2 * q][0]), "=r"(b[2 * q][1]),
                      "=r"(b[2 * q + 1][0]), "=r"(b[2 * q + 1][1])
                    : "r"(stB + offB[q] + kb));
            }
            #pragma unroll
            for (int mt = 0; mt < 2; mt++)
                #pragma unroll
                for (int nt = 0; nt < 8; nt++) {
                    asm volatile(
                        "mma.sync.aligned.m16n8k16.row.col.f32.f16.f16.f32 "
                        "{%0,%1,%2,%3}, {%4,%5,%6,%7}, {%8,%9}, {%0,%1,%2,%3};"
                        : "+f"(c[mt][nt][0]), "+f"(c[mt][nt][1]),
                          "+f"(c[mt][nt][2]), "+f"(c[mt][nt][3])
                        : "r"(a[mt][0]), "r"(a[mt][1]), "r"(a[mt][2]), "r"(a[mt][3]),
                          "r"(b[nt][0]), "r"(b[nt][1]));
                }
        }
    }

    #pragma unroll
    for (int mt = 0; mt < 2; mt++) {
        int r0 = bRow + warp_m * 32 + mt * 16 + gid;
        int r1 = r0 + 8;
        #pragma unroll
        for (int nt = 0; nt < 8; nt++) {
            int gcol = bCol + warp_n * 64 + nt * 8 + 2 * tig;
            if (r0 < M)
                *(__half2*)(g_Yh + (size_t)r0 * DOUT + gcol) =
                    __floats2half2_rn(c[mt][nt][0], c[mt][nt][1]);
            if (r1 < M)
                *(__half2*)(g_Yh + (size_t)r1 * DOUT + gcol) =
                    __floats2half2_rn(c[mt][nt][2], c[mt][nt][3]);
        }
    }
}

// ---- host-side resources, created before harness checkpoints ----
static cudaStream_t g_s2;
static cudaEvent_t  g_evFork, g_evSort, g_evWt;
namespace {
struct _HostInit {
    _HostInit() {
        cudaStreamCreateWithFlags(&g_s2, cudaStreamNonBlocking);
        cudaEventCreateWithFlags(&g_evFork, cudaEventDisableTiming);
        cudaEventCreateWithFlags(&g_evSort, cudaEventDisableTiming);
        cudaEventCreateWithFlags(&g_evWt,   cudaEventDisableTiming);
        cudaFuncSetAttribute(gemm_f16, cudaFuncAttributeMaxDynamicSharedMemorySize,
                             SMEM_BYTES);
    }
} _hostInit;
}

// ---------------------------------------------------------------------------
// Counting-sort pipeline (forked stream)
// ---------------------------------------------------------------------------
__global__ void zero_cnt(int n) {
    int i = blockIdx.x * blockDim.x + threadIdx.x;
    if (i < n) g_cnt[i] = 0;
}

__global__ void hist2(const int* __restrict__ r1, int n1,
                      const int* __restrict__ r2, int n2) {
    int i = blockIdx.x * blockDim.x + threadIdx.x;
    if (i < n1) {
        atomicAdd(&g_cnt[__ldcs(r1 + i)], 1);
    } else {
        int j = i - n1;
        if (j < n2) atomicAdd(&g_cnt[__ldcs(r2 + j)], 1);
    }
}

__global__ void scan_local(int n) {
    __shared__ int buf[1024];
    int tid = threadIdx.x;
    int i = blockIdx.x * 1024 + tid;
    int v = (i < n) ? g_cnt[i] : 0;
    buf[tid] = v;
    __syncthreads();
    #pragma unroll
    for (int s = 1; s < 1024; s <<= 1) {
        int t = (tid >= s) ? buf[tid - s] : 0;
        __syncthreads();
        buf[tid] += t;
        __syncthreads();
    }
    if (i < n) g_start[i] = buf[tid] - v;
    if (tid == 1023) g_bsum[blockIdx.x] = buf[1023];
}

__global__ void scan_bsum(int nb) {
    __shared__ int buf[128];
    int tid = threadIdx.x;
    int v = (tid < nb) ? g_bsum[tid] : 0;
    buf[tid] = v;
    __syncthreads();
    #pragma unroll
    for (int s = 1; s < 128; s <<= 1) {
        int t = (tid >= s) ? buf[tid - s] : 0;
        __syncthreads();
        buf[tid] += t;
        __syncthreads();
    }
    if (tid < nb) g_bsum[tid] = buf[tid] - v;
}

__global__ void scan_add(int n) {
    int i = blockIdx.x * 1024 + threadIdx.x;
    if (i < n) {
        int s = g_start[i] + g_bsum[blockIdx.x];
        g_start[i] = s;
        g_cur[i]   = s;
    }
}

__global__ void fill2(const int* __restrict__ r1, const int* __restrict__ c1,
                      const float* __restrict__ v1, int n1,
                      const int* __restrict__ r2, const int* __restrict__ c2,
                      const float* __restrict__ v2, int n2) {
    int i = blockIdx.x * blockDim.x + threadIdx.x;
    if (i < n1) {
        int r = __ldcs(r1 + i);
        int p = atomicAdd(&g_cur[r], 1);
        g_edges[p] = make_float2(__int_as_float(__ldcs(c1 + i)), __ldcs(v1 + i));
    } else {
        int j = i - n1;
        if (j < n2) {
            int r = __ldcs(r2 + j);
            int p = atomicAdd(&g_cur[r], 1);
            g_edges[p] = make_float2(__int_as_float(__ldcs(c2 + j)), __ldcs(v2 + j));
        }
    }
}

// ---------------------------------------------------------------------------
// Accumulate: one warp per row. out[row,:] = bias + sum_j val_j * Yh[col_j,:]
// 8-edge unroll for deeper gather MLP.
// ---------------------------------------------------------------------------
__global__ void accumulate(const float* __restrict__ bias, float* __restrict__ out, int M) {
    int row  = (blockIdx.x * blockDim.x + threadIdx.x) >> 5;
    if (row >= M) return;
    int lane = threadIdx.x & 31;

    int beg = g_start[row];
    int end = g_cur[row];

    float acc[8];
    *(float4*)(acc)     = ((const float4*)bias)[lane * 2];
    *(float4*)(acc + 4) = ((const float4*)bias)[lane * 2 + 1];

    int j = beg;
    for (; j + 7 < end; j += 8) {
        float2 e[8];
        #pragma unroll
        for (int u = 0; u < 8; u++) e[u] = __ldcs(&g_edges[j + u]);
        uint4 q[8];
        #pragma unroll
        for (int u = 0; u < 8; u++) {
            int c = __float_as_int(e[u].x);
            q[u] = __ldg((const uint4*)(g_Yh + (size_t)c * DOUT + lane * 8));
        }
        #pragma unroll
        for (int u = 0; u < 8; u++) {
            float v = e[u].y;
            const __half2* h = (const __half2*)&q[u];
            #pragma unroll
            for (int p = 0; p < 4; p++) {
                float2 f = __half22float2(h[p]);
                acc[2 * p]     += v * f.x;
                acc[2 * p + 1] += v * f.y;
            }
        }
    }
    for (; j < end; j++) {
        float2 e = __ldcs(&g_edges[j]);
        int c = __float_as_int(e.x);  float v = e.y;
        uint4 q = __ldg((const uint4*)(g_Yh + (size_t)c * DOUT + lane * 8));
        const __half2* h = (const __half2*)&q;
        #pragma unroll
        for (int p = 0; p < 4; p++) {
            float2 f = __half22float2(h[p]);
            acc[2 * p]     += v * f.x;
            acc[2 * p + 1] += v * f.y;
        }
    }

    float4* o = (float4*)(out + (size_t)row * DOUT);
    __stcs(o + lane * 2,     *(float4*)(acc));
    __stcs(o + lane * 2 + 1, *(float4*)(acc + 4));
}

// ---------------------------------------------------------------------------
extern "C" void kernel_launch(void* const* d_in, const int* in_sizes, int n_in,
                              void* d_out, int out_size) {
    const float* X    = (const float*)d_in[0];
    const int*   Lr   = (const int*)d_in[1];
    const int*   Lc   = (const int*)d_in[2];
    const float* Lv   = (const float*)d_in[3];
    const int*   L3r  = (const int*)d_in[4];
    const int*   L3c  = (const int*)d_in[5];
    const float* L3v  = (const float*)d_in[6];
    const float* Wt   = (const float*)d_in[7];
    const float* bias = (const float*)d_in[8];
    float* out = (float*)d_out;

    int M    = in_sizes[0] / DIN;   // 100000
    int nnz1 = in_sizes[1];
    int nnz2 = in_sizes[4];
    int nnzT = nnz1 + nnz2;

    // ---- fork: cvt_wt + sort on s2 ----
    cudaEventRecord(g_evFork, 0);
    cudaStreamWaitEvent(g_s2, g_evFork, 0);

    cvt_wt<<<(DIN * DOUT + 255) / 256, 256, 0, g_s2>>>(Wt);
    cudaEventRecord(g_evWt, g_s2);

    int nblk = (M + 1023) / 1024;
    zero_cnt<<<(M + 255) / 256, 256, 0, g_s2>>>(M);
    hist2<<<(nnzT + 255) / 256, 256, 0, g_s2>>>(Lr, nnz1, L3r, nnz2);
    scan_local<<<nblk, 1024, 0, g_s2>>>(M);
    scan_bsum<<<1, 128, 0, g_s2>>>(nblk);
    scan_add<<<nblk, 1024, 0, g_s2>>>(M);
    fill2<<<(nnzT + 255) / 256, 256, 0, g_s2>>>(Lr, Lc, Lv, nnz1, L3r, L3c, L3v, nnz2);
    cudaEventRecord(g_evSort, g_s2);

    // ---- main: cvt_x, then GEMM (waits for cvt_wt), then accumulate ----
    int x8 = M * (DIN / 8);
    cvt_x<<<(x8 + 255) / 256, 256>>>(X, x8);

    cudaStreamWaitEvent(0, g_evWt, 0);
    dim3 ggrid(2, (M + 127) / 128);
    gemm_f16<<<ggrid, 256, SMEM_BYTES>>>(M);

    cudaStreamWaitEvent(0, g_evSort, 0);
    int blocks = (M * 32 + 255) / 256;
    accumulate<<<blocks, 256>>>(bias, out, M);
}

// round 15
// speedup vs baseline: 1.0590x; 1.0032x over previous
#include <cuda_runtime.h>
#include <cuda_fp16.h>
#include <cstdint>

#define N_NODES 100000
#define DIN 256
#define DOUT 256
#define MAX_EDGES 6400000

#define BSTAGES 3
#define SW 20                        // tile row stride in words (80B)
#define A_STG (128 * SW)             // words per A stage (2 stages)
#define B_STG (128 * SW)             // words per B stage (3 stages)
#define SMEM_BYTES ((2 * A_STG + BSTAGES * B_STG) * 4)   // 51200

// ---- device-global scratch (allocation-free) ----
__device__ __half g_Wth[DIN * DOUT];             // fp16(W^T) [n][k]
__device__ __half g_Yh[(size_t)N_NODES * DOUT];  // fp16(X @ W)
__device__ float2 g_edges[MAX_EDGES];
__device__ int    g_cnt[N_NODES];
__device__ int    g_start[N_NODES];
__device__ int    g_cur[N_NODES];
__device__ int    g_bsum[128];

// ---------------------------------------------------------------------------
__device__ __forceinline__ void cp16(uint32_t dst, const void* src, int bytes) {
    asm volatile("cp.async.cg.shared.global [%0], [%1], 16, %2;"
                 :: "r"(dst), "l"(src), "r"(bytes));
}

// g_Wth[n][k] = fp16(W[k][n])
__global__ void cvt_wt(const float* __restrict__ W) {
    int idx = blockIdx.x * blockDim.x + threadIdx.x;
    int n = idx >> 8, k = idx & 255;
    g_Wth[idx] = __float2half_rn(W[k * DOUT + n]);
}

// ---------------------------------------------------------------------------
// GEMM: g_Yh = fp16(X @ W) via fp16 mma.sync.m16n8k16 (fp32 accumulate)
// 128x128 block tile, BK=32, 256 thr (8 warps 4x2).
// A: fp32 LDG -> cvt fp16 -> STS, register double-buffered (fuses cvt_x).
// B: 3-stage cp.async from fp16 W^T.  ldmatrix.x4 frag loads (80B stride).
// ---------------------------------------------------------------------------
__global__ __launch_bounds__(256, 2)
void gemm_f16(const float* __restrict__ X, int M) {
    extern __shared__ uint32_t smem[];
    uint32_t* Asm = smem;                  // 2 * A_STG words
    uint32_t* Bsm = smem + 2 * A_STG;      // BSTAGES * B_STG words

    int t = threadIdx.x;
    int lane = t & 31, wid = t >> 5;
    int warp_m = wid & 3;
    int warp_n = wid >> 2;
    int gid = lane >> 2;
    int tig = lane & 3;

    int bRow = blockIdx.y * 128;
    int bCol = blockIdx.x * 128;

    // loaders: row = t>>1 (0..127), half = t&1 (16 k-values each)
    int l_r = t >> 1, l_h = t & 1;
    int growA = bRow + l_r;
    const float* aSrc = X + (size_t)(growA < M ? growA : 0) * DIN + l_h * 16;
    const __half* bSrc = g_Wth + (size_t)(bCol + l_r) * DIN + l_h * 16;

    uint32_t* aDst[2];
    uint32_t bD[BSTAGES];
    #pragma unroll
    for (int s = 0; s < 2; s++)
        aDst[s] = Asm + s * A_STG + l_r * SW + l_h * 8;
    #pragma unroll
    for (int s = 0; s < BSTAGES; s++)
        bD[s] = (uint32_t)__cvta_generic_to_shared(Bsm + s * B_STG + l_r * SW + l_h * 8);

    // ldmatrix lane offsets (bytes, relative to stage base)
    int lj = lane >> 3;
    int lr = lane & 7;
    uint32_t offA[2];
    #pragma unroll
    for (int mt = 0; mt < 2; mt++) {
        int row = warp_m * 32 + mt * 16 + (lj & 1) * 8 + lr;
        offA[mt] = row * (SW * 4) + (lj >> 1) * 16;
    }
    uint32_t offB[4];
    #pragma unroll
    for (int q = 0; q < 4; q++) {
        int nrow = warp_n * 64 + q * 16 + (lj >> 1) * 8 + lr;
        offB[q] = nrow * (SW * 4) + (lj & 1) * 16;
    }
    uint32_t aBase = (uint32_t)__cvta_generic_to_shared(Asm);
    uint32_t bBase = (uint32_t)__cvta_generic_to_shared(Bsm);

    float c[2][8][4] = {};

    const int NIT = DIN / 32;   // 8

    // ---- prologue ----
    float4 ar[4];
    #pragma unroll
    for (int q = 0; q < 4; q++) ar[q] = *(const float4*)(aSrc + q * 4);   // A k0=0

    #pragma unroll
    for (int s = 0; s < BSTAGES - 1; s++) {
        int k0 = s * 32;
        cp16(bD[s],      bSrc + k0,     16);
        cp16(bD[s] + 16, bSrc + k0 + 8, 16);
        asm volatile("cp.async.commit_group;");
    }

    #pragma unroll
    for (int it = 0; it < NIT; it++) {
        int p = it & 1;

        // STS current A stage (convert in registers)
        {
            const float* f = (const float*)ar;
            uint32_t hw[8];
            #pragma unroll
            for (int j = 0; j < 8; j++) {
                __half2 h = __floats2half2_rn(f[2 * j], f[2 * j + 1]);
                hw[j] = *(uint32_t*)&h;
            }
            uint4* dst = (uint4*)aDst[p];
            dst[0] = make_uint4(hw[0], hw[1], hw[2], hw[3]);
            dst[1] = make_uint4(hw[4], hw[5], hw[6], hw[7]);
        }

        // prefetch next A stage into registers
        if (it + 1 < NIT) {
            const float* p2 = aSrc + (it + 1) * 32;
            #pragma unroll
            for (int q = 0; q < 4; q++) ar[q] = *(const float4*)(p2 + q * 4);
        }

        asm volatile("cp.async.wait_group %0;" :: "n"(BSTAGES - 2));
        __syncthreads();

        // prefetch next B stage
        int kt = it + BSTAGES - 1;
        if (kt < NIT) {
            int s = kt % BSTAGES;
            int k0 = kt * 32;
            cp16(bD[s],      bSrc + k0,     16);
            cp16(bD[s] + 16, bSrc + k0 + 8, 16);
        }
        asm volatile("cp.async.commit_group;");

        uint32_t stA = aBase + p * (A_STG * 4);
        uint32_t stB = bBase + (it % BSTAGES) * (B_STG * 4);

        #pragma unroll
        for (int ks = 0; ks < 2; ks++) {
            uint32_t kb = ks * 32;   // 16 halfs = 32 bytes
            uint32_t a[2][4];
            #pragma unroll
            for (int mt = 0; mt < 2; mt++) {
                asm volatile(
                    "ldmatrix.sync.aligned.m8n8.x4.shared.b16 {%0,%1,%2,%3}, [%4];"
                    : "=r"(a[mt][0]), "=r"(a[mt][1]), "=r"(a[mt][2]), "=r"(a[mt][3])
                    : "r"(stA + offA[mt] + kb));
            }
            uint32_t b[8][2];
            #pragma unroll
            for (int q = 0; q < 4; q++) {
                asm volatile(
                    "ldmatrix.sync.aligned.m8n8.x4.shared.b16 {%0,%1,%2,%3}, [%4];"
                    : "=r"(b[2 * q][0]), "=r"(b[2 * q][1]),
                      "=r"(b[2 * q + 1][0]), "=r"(b[2 * q + 1][1])
                    : "r"(stB + offB[q] + kb));
            }
            #pragma unroll
            for (int mt = 0; mt < 2; mt++)
                #pragma unroll
                for (int nt = 0; nt < 8; nt++) {
                    asm volatile(
                        "mma.sync.aligned.m16n8k16.row.col.f32.f16.f16.f32 "
                        "{%0,%1,%2,%3}, {%4,%5,%6,%7}, {%8,%9}, {%0,%1,%2,%3};"
                        : "+f"(c[mt][nt][0]), "+f"(c[mt][nt][1]),
                          "+f"(c[mt][nt][2]), "+f"(c[mt][nt][3])
                        : "r"(a[mt][0]), "r"(a[mt][1]), "r"(a[mt][2]), "r"(a[mt][3]),
                          "r"(b[nt][0]), "r"(b[nt][1]));
                }
        }
    }

    #pragma unroll
    for (int mt = 0; mt < 2; mt++) {
        int r0 = bRow + warp_m * 32 + mt * 16 + gid;
        int r1 = r0 + 8;
        #pragma unroll
        for (int nt = 0; nt < 8; nt++) {
            int gcol = bCol + warp_n * 64 + nt * 8 + 2 * tig;
            if (r0 < M)
                *(__half2*)(g_Yh + (size_t)r0 * DOUT + gcol) =
                    __floats2half2_rn(c[mt][nt][0], c[mt][nt][1]);
            if (r1 < M)
                *(__half2*)(g_Yh + (size_t)r1 * DOUT + gcol) =
                    __floats2half2_rn(c[mt][nt][2], c[mt][nt][3]);
        }
    }
}

// ---- host-side resources, created before harness checkpoints ----
static cudaStream_t g_s2;
static cudaEvent_t  g_evFork, g_evSort, g_evWt;
namespace {
struct _HostInit {
    _HostInit() {
        cudaStreamCreateWithFlags(&g_s2, cudaStreamNonBlocking);
        cudaEventCreateWithFlags(&g_evFork, cudaEventDisableTiming);
        cudaEventCreateWithFlags(&g_evSort, cudaEventDisableTiming);
        cudaEventCreateWithFlags(&g_evWt,   cudaEventDisableTiming);
        cudaFuncSetAttribute(gemm_f16, cudaFuncAttributeMaxDynamicSharedMemorySize,
                             SMEM_BYTES);
    }
} _hostInit;
}

// ---------------------------------------------------------------------------
// Counting-sort pipeline (forked stream)
// ---------------------------------------------------------------------------
__global__ void zero_cnt(int n) {
    int i = blockIdx.x * blockDim.x + threadIdx.x;
    if (i < n) g_cnt[i] = 0;
}

__global__ void hist2(const int* __restrict__ r1, int n1,
                      const int* __restrict__ r2, int n2) {
    int i = blockIdx.x * blockDim.x + threadIdx.x;
    if (i < n1) {
        atomicAdd(&g_cnt[__ldcs(r1 + i)], 1);
    } else {
        int j = i - n1;
        if (j < n2) atomicAdd(&g_cnt[__ldcs(r2 + j)], 1);
    }
}

__global__ void scan_local(int n) {
    __shared__ int buf[1024];
    int tid = threadIdx.x;
    int i = blockIdx.x * 1024 + tid;
    int v = (i < n) ? g_cnt[i] : 0;
    buf[tid] = v;
    __syncthreads();
    #pragma unroll
    for (int s = 1; s < 1024; s <<= 1) {
        int t = (tid >= s) ? buf[tid - s] : 0;
        __syncthreads();
        buf[tid] += t;
        __syncthreads();
    }
    if (i < n) g_start[i] = buf[tid] - v;
    if (tid == 1023) g_bsum[blockIdx.x] = buf[1023];
}

__global__ void scan_bsum(int nb) {
    __shared__ int buf[128];
    int tid = threadIdx.x;
    int v = (tid < nb) ? g_bsum[tid] : 0;
    buf[tid] = v;
    __syncthreads();
    #pragma unroll
    for (int s = 1; s < 128; s <<= 1) {
        int t = (tid >= s) ? buf[tid - s] : 0;
        __syncthreads();
        buf[tid] += t;
        __syncthreads();
    }
    if (tid < nb) g_bsum[tid] = buf[tid] - v;
}

__global__ void scan_add(int n) {
    int i = blockIdx.x * 1024 + threadIdx.x;
    if (i < n) {
        int s = g_start[i] + g_bsum[blockIdx.x];
        g_start[i] = s;
        g_cur[i]   = s;
    }
}

__global__ void fill2(const int* __restrict__ r1, const int* __restrict__ c1,
                      const float* __restrict__ v1, int n1,
                      const int* __restrict__ r2, const int* __restrict__ c2,
                      const float* __restrict__ v2, int n2) {
    int i = blockIdx.x * blockDim.x + threadIdx.x;
    if (i < n1) {
        int r = __ldcs(r1 + i);
        int p = atomicAdd(&g_cur[r], 1);
        g_edges[p] = make_float2(__int_as_float(__ldcs(c1 + i)), __ldcs(v1 + i));
    } else {
        int j = i - n1;
        if (j < n2) {
            int r = __ldcs(r2 + j);
            int p = atomicAdd(&g_cur[r], 1);
            g_edges[p] = make_float2(__int_as_float(__ldcs(c2 + j)), __ldcs(v2 + j));
        }
    }
}

// ---------------------------------------------------------------------------
// Accumulate: one warp per row. out[row,:] = bias + sum_j val_j * Yh[col_j,:]
// 8-edge unroll for deep gather MLP.
// ---------------------------------------------------------------------------
__global__ void accumulate(const float* __restrict__ bias, float* __restrict__ out, int M) {
    int row  = (blockIdx.x * blockDim.x + threadIdx.x) >> 5;
    if (row >= M) return;
    int lane = threadIdx.x & 31;

    int beg = g_start[row];
    int end = g_cur[row];

    float acc[8];
    *(float4*)(acc)     = ((const float4*)bias)[lane * 2];
    *(float4*)(acc + 4) = ((const float4*)bias)[lane * 2 + 1];

    int j = beg;
    for (; j + 7 < end; j += 8) {
        float2 e[8];
        #pragma unroll
        for (int u = 0; u < 8; u++) e[u] = __ldcs(&g_edges[j + u]);
        uint4 q[8];
        #pragma unroll
        for (int u = 0; u < 8; u++) {
            int c = __float_as_int(e[u].x);
            q[u] = __ldg((const uint4*)(g_Yh + (size_t)c * DOUT + lane * 8));
        }
        #pragma unroll
        for (int u = 0; u < 8; u++) {
            float v = e[u].y;
            const __half2* h = (const __half2*)&q[u];
            #pragma unroll
            for (int p = 0; p < 4; p++) {
                float2 f = __half22float2(h[p]);
                acc[2 * p]     += v * f.x;
                acc[2 * p + 1] += v * f.y;
            }
        }
    }
    for (; j < end; j++) {
        float2 e = __ldcs(&g_edges[j]);
        int c = __float_as_int(e.x);  float v = e.y;
        uint4 q = __ldg((const uint4*)(g_Yh + (size_t)c * DOUT + lane * 8));
        const __half2* h = (const __half2*)&q;
        #pragma unroll
        for (int p = 0; p < 4; p++) {
            float2 f = __half22float2(h[p]);
            acc[2 * p]     += v * f.x;
            acc[2 * p + 1] += v * f.y;
        }
    }

    float4* o = (float4*)(out + (size_t)row * DOUT);
    __stcs(o + lane * 2,     *(float4*)(acc));
    __stcs(o + lane * 2 + 1, *(float4*)(acc + 4));
}

// ---------------------------------------------------------------------------
extern "C" void kernel_launch(void* const* d_in, const int* in_sizes, int n_in,
                              void* d_out, int out_size) {
    const float* X    = (const float*)d_in[0];
    const int*   Lr   = (const int*)d_in[1];
    const int*   Lc   = (const int*)d_in[2];
    const float* Lv   = (const float*)d_in[3];
    const int*   L3r  = (const int*)d_in[4];
    const int*   L3c  = (const int*)d_in[5];
    const float* L3v  = (const float*)d_in[6];
    const float* Wt   = (const float*)d_in[7];
    const float* bias = (const float*)d_in[8];
    float* out = (float*)d_out;

    int M    = in_sizes[0] / DIN;   // 100000
    int nnz1 = in_sizes[1];
    int nnz2 = in_sizes[4];
    int nnzT = nnz1 + nnz2;

    // ---- fork: cvt_wt + sort on s2 ----
    cudaEventRecord(g_evFork, 0);
    cudaStreamWaitEvent(g_s2, g_evFork, 0);

    cvt_wt<<<(DIN * DOUT + 255) / 256, 256, 0, g_s2>>>(Wt);
    cudaEventRecord(g_evWt, g_s2);

    int nblk = (M + 1023) / 1024;
    zero_cnt<<<(M + 255) / 256, 256, 0, g_s2>>>(M);
    hist2<<<(nnzT + 255) / 256, 256, 0, g_s2>>>(Lr, nnz1, L3r, nnz2);
    scan_local<<<nblk, 1024, 0, g_s2>>>(M);
    scan_bsum<<<1, 128, 0, g_s2>>>(nblk);
    scan_add<<<nblk, 1024, 0, g_s2>>>(M);
    fill2<<<(nnzT + 255) / 256, 256, 0, g_s2>>>(Lr, Lc, Lv, nnz1, L3r, L3c, L3v, nnz2);
    cudaEventRecord(g_evSort, g_s2);

    // ---- main: GEMM (waits for cvt_wt; reads X fp32 directly), accumulate ----
    cudaStreamWaitEvent(0, g_evWt, 0);
    dim3 ggrid(2, (M + 127) / 128);
    gemm_f16<<<ggrid, 256, SMEM_BYTES>>>(X, M);

    cudaStreamWaitEvent(0, g_evSort, 0);
    int blocks = (M * 32 + 255) / 256;
    accumulate<<<blocks, 256>>>(bias, out, M);
}